// round 15
// baseline (speedup 1.0000x reference)
#include <cuda_runtime.h>

#define TS   32          // output tile (TS x TS)
#define HALO 5
#define IN   42          // TS + 2*HALO
#define INS  44          // padded smem row stride for input arrays (mult of 4)
#define IMH  512
#define IMW  512
#define NPLANES (32*3)
#define NPIX    ((long long)NPLANES * IMH * IMW)   // 25165824

// Normalized 11-tap Gaussian (sigma=1.5), compile-time so taps become FFMA-imm.
__device__ constexpr float GW[11] = {
    0.00102838f, 0.00759876f, 0.03600077f, 0.10936071f, 0.21300550f,
    0.26601172f,
    0.21300550f, 0.10936071f, 0.03600077f, 0.00759876f, 0.00102838f
};

// [0] = sum |x-y|, [1] = sum ssim_map. Zero-initialized at module load;
// finalize_kernel resets them after reading, so every replay starts from 0.
__device__ double g_acc[2] = {0.0, 0.0};

// Sliding-window conv on a 16-value register window: outputs cols j..j+3.
__device__ __forceinline__ void conv16to4(const float* __restrict__ v, float4& out)
{
    float o0 = 0.f, o1 = 0.f, o2 = 0.f, o3 = 0.f;
#pragma unroll
    for (int k = 0; k < 11; k++) {
        float w = GW[k];
        o0 += w * v[k];
        o1 += w * v[k + 1];
        o2 += w * v[k + 2];
        o3 += w * v[k + 3];
    }
    out.x = o0; out.y = o1; out.z = o2; out.w = o3;
}

__global__ __launch_bounds__(256, 4) void ssim_l1_kernel(
    const float* __restrict__ pred, const float* __restrict__ tgt)
{
    extern __shared__ float sm[];
    float* sX = sm;                   // IN*INS each (raw inputs only)
    float* sY = sX + IN * INS;
    float* hX = sY + IN * INS;        // IN*TS each (H-pass results)
    float* hY = hX + IN * TS;
    float* hP = hY + IN * TS;         // H-conv of x^2+y^2
    float* hQ = hP + IN * TS;         // H-conv of x*y

    const int tid  = threadIdx.x;
    const int wid  = tid >> 5;        // warp 0..7
    const int lane = tid & 31;
    const int plane = blockIdx.z;
    const float* __restrict__ px = pred + (size_t)plane * (IMH * IMW);
    const float* __restrict__ py = tgt  + (size_t)plane * (IMH * IMW);
    const int bx0 = blockIdx.x * TS - HALO;
    const int by0 = blockIdx.y * TS - HALO;

    // ---- Phase 1 (per-warp): warp w loads rows {r : r mod 8 == w}.
    //      L1 folded for interior pixels (each pixel interior of one tile).
    float l1 = 0.f;
#pragma unroll
    for (int it = 0; it < 6; it++) {
        int r = wid + it * 8;
        if (r < IN) {
            int gy = by0 + r;
            bool rowok = (unsigned)gy < IMH;
            // col = lane
            {
                int c = lane;
                int gx = bx0 + c;
                float x = 0.f, y = 0.f;
                if (rowok && (unsigned)gx < IMW) {
                    int o = gy * IMW + gx;
                    x = px[o];
                    y = py[o];
                }
                sX[r * INS + c] = x;
                sY[r * INS + c] = y;
                if (r >= HALO && r < IN - HALO && c >= HALO && c < IN - HALO)
                    l1 += fabsf(x - y);
            }
            // col = lane + 32 (only lanes 0..9)
            {
                int c = lane + 32;
                if (c < IN) {
                    int gx = bx0 + c;
                    float x = 0.f, y = 0.f;
                    if (rowok && (unsigned)gx < IMW) {
                        int o = gy * IMW + gx;
                        x = px[o];
                        y = py[o];
                    }
                    sX[r * INS + c] = x;
                    sY[r * INS + c] = y;
                    if (r >= HALO && r < IN - HALO && c >= HALO && c < IN - HALO)
                        l1 += fabsf(x - y);
                }
            }
        }
    }
    __syncwarp();   // own-warp rows visible; no cross-warp dependency yet

    // ---- Phase 2 (per-warp): H-pass over the SAME owned rows.
    //      lane = row_sub*8 + group: 4 rows x 8 four-col groups per iteration.
    {
        int row_sub = lane >> 3;      // 0..3
        int g  = lane & 7;            // col-group 0..7
        int c0 = g * 4;
#pragma unroll
        for (int it = 0; it < 2; it++) {
            int r = wid + (it * 4 + row_sub) * 8;
            if (r < IN) {
                int b  = r * INS + c0;   // 16B-aligned
                int ho = r * TS + c0;    // 16B-aligned

                float xv[16], yv[16];
                {
                    const float4* p4 = reinterpret_cast<const float4*>(sX + b);
#pragma unroll
                    for (int j = 0; j < 4; j++) {
                        float4 a = p4[j];
                        xv[4*j] = a.x; xv[4*j+1] = a.y; xv[4*j+2] = a.z; xv[4*j+3] = a.w;
                    }
                    const float4* q4 = reinterpret_cast<const float4*>(sY + b);
#pragma unroll
                    for (int j = 0; j < 4; j++) {
                        float4 a = q4[j];
                        yv[4*j] = a.x; yv[4*j+1] = a.y; yv[4*j+2] = a.z; yv[4*j+3] = a.w;
                    }
                }
                float4 o;
                conv16to4(xv, o); *reinterpret_cast<float4*>(hX + ho) = o;
                conv16to4(yv, o); *reinterpret_cast<float4*>(hY + ho) = o;
                // overwrite windows in place: xv <- x^2+y^2, yv <- x*y
#pragma unroll
                for (int j = 0; j < 16; j++) {
                    float x = xv[j], y = yv[j];
                    float q = x * y;
                    xv[j] = x * x + y * y;
                    yv[j] = q;
                }
                conv16to4(xv, o); *reinterpret_cast<float4*>(hP + ho) = o;
                conv16to4(yv, o); *reinterpret_cast<float4*>(hQ + ho) = o;
            }
        }
    }
    __syncthreads();   // the ONLY full-tile barrier before the V-pass

    // ---- Phase 3: vertical pass (streaming scatter-accumulate) + SSIM.
    //      32 cols x 8 groups of 4 rows = exactly 256 threads, all active.
    //      Warp lanes -> consecutive cols: conflict-free.
    float ssim = 0.f;
    {
        int c  = tid & 31;
        int r0 = (tid >> 5) * 4;
        int b  = r0 * TS + c;

        float m1[4], m2[4], ep[4], eq[4];
#pragma unroll
        for (int m = 0; m < 4; m++) { m1[m] = 0.f; m2[m] = 0.f; ep[m] = 0.f; eq[m] = 0.f; }

#pragma unroll
        for (int j = 0; j < 14; j++) {
            int o = b + j * TS;
            float vx = hX[o];
            float vy = hY[o];
            float vp = hP[o];
            float vq = hQ[o];
#pragma unroll
            for (int m = 0; m < 4; m++) {
                int k = j - m;
                if (k >= 0 && k <= 10) {
                    float w = GW[k];
                    m1[m] += w * vx;
                    m2[m] += w * vy;
                    ep[m] += w * vp;
                    eq[m] += w * vq;
                }
            }
        }
#pragma unroll
        for (int j = 0; j < 4; j++) {
            float m11 = m1[j] * m1[j];
            float m22 = m2[j] * m2[j];
            float m12 = m1[j] * m2[j];
            float s12 = eq[j] - m12;          // sigma12
            float sss = ep[j] - m11 - m22;    // sigma1_sq + sigma2_sq
            const float C1 = 1e-4f;   // 0.01^2
            const float C2 = 9e-4f;   // 0.03^2
            float num = (2.f * m12 + C1) * (2.f * s12 + C2);
            float den = (m11 + m22 + C1) * (sss + C2);
            ssim += __fdividef(num, den);
        }
    }

    // ---- Block reduction of (l1, ssim), then one atomicAdd pair per block.
#pragma unroll
    for (int off = 16; off > 0; off >>= 1) {
        l1   += __shfl_down_sync(0xffffffffu, l1,   off);
        ssim += __shfl_down_sync(0xffffffffu, ssim, off);
    }
    __syncthreads();            // sX region must be dead before reuse
    if (lane == 0) {
        sX[wid]     = l1;
        sX[8 + wid] = ssim;
    }
    __syncthreads();
    if (tid == 0) {
        double a = 0.0, b = 0.0;
#pragma unroll
        for (int w = 0; w < 8; w++) { a += (double)sX[w]; b += (double)sX[8 + w]; }
        atomicAdd(&g_acc[0], a);
        atomicAdd(&g_acc[1], b);
    }
}

__global__ void finalize_kernel(float* __restrict__ out) {
    const double n = (double)NPIX;
    double l1 = g_acc[0] / n;
    double ss = g_acc[1] / n;
    out[0] = (float)(0.84 * l1 + (1.0 - 0.84) * (1.0 - ss));
    g_acc[0] = 0.0;   // reset for the next replay (keeps launches deterministic)
    g_acc[1] = 0.0;
}

extern "C" void kernel_launch(void* const* d_in, const int* in_sizes, int n_in,
                              void* d_out, int out_size)
{
    const float* pred = (const float*)d_in[0];
    const float* tgt  = (const float*)d_in[1];
    float* out = (float*)d_out;

    const int smem_bytes = (2 * IN * INS + 4 * IN * TS) * (int)sizeof(float); // 36288
    cudaFuncSetAttribute(ssim_l1_kernel,
                         cudaFuncAttributeMaxDynamicSharedMemorySize, smem_bytes);

    dim3 grid(IMW / TS, IMH / TS, NPLANES);   // 16 x 16 x 96
    ssim_l1_kernel<<<grid, 256, smem_bytes>>>(pred, tgt);
    finalize_kernel<<<1, 1>>>(out);
}

// round 16
// speedup vs baseline: 1.2259x; 1.2259x over previous
#include <cuda_runtime.h>

#define TS   32          // output tile (TS x TS)
#define HALO 5
#define IN   42          // TS + 2*HALO
#define INS  44          // padded smem row stride for input arrays (mult of 4)
#define IMH  512
#define IMW  512
#define NPLANES (32*3)
#define NPIX    ((long long)NPLANES * IMH * IMW)   // 25165824
#define NTILES  (16 * 16 * NPLANES)               // 24576
#define GRID    592                               // 148 SM x 4 CTA: one wave

// Normalized 11-tap Gaussian (sigma=1.5), compile-time so taps become FFMA-imm.
__device__ constexpr float GW[11] = {
    0.00102838f, 0.00759876f, 0.03600077f, 0.10936071f, 0.21300550f,
    0.26601172f,
    0.21300550f, 0.10936071f, 0.03600077f, 0.00759876f, 0.00102838f
};

// [0] = sum |x-y|, [1] = sum ssim_map. Zero-initialized at module load;
// finalize_kernel resets them after reading, so every replay starts from 0.
__device__ double g_acc[2] = {0.0, 0.0};

// Sliding-window conv on a 16-value register window: outputs cols j..j+3.
__device__ __forceinline__ void conv16to4(const float* __restrict__ v, float4& out)
{
    float o0 = 0.f, o1 = 0.f, o2 = 0.f, o3 = 0.f;
#pragma unroll
    for (int k = 0; k < 11; k++) {
        float w = GW[k];
        o0 += w * v[k];
        o1 += w * v[k + 1];
        o2 += w * v[k + 2];
        o3 += w * v[k + 3];
    }
    out.x = o0; out.y = o1; out.z = o2; out.w = o3;
}

// Load tile t's 42x42 halo region into sX/sY; fold L1 for interior pixels.
__device__ __forceinline__ void load_tile(
    int t, int tid, const float* __restrict__ pred, const float* __restrict__ tgt,
    float* __restrict__ sX, float* __restrict__ sY, float& l1)
{
    int plane = t >> 8;               // 256 tiles per plane (16x16)
    int rem   = t & 255;
    int by0   = (rem >> 4) * TS - HALO;
    int bx0   = (rem & 15) * TS - HALO;
    const float* __restrict__ px = pred + (size_t)plane * (IMH * IMW);
    const float* __restrict__ py = tgt  + (size_t)plane * (IMH * IMW);

    for (int i = tid; i < IN * IN; i += 256) {
        int r = i / IN;
        int c = i - r * IN;
        int gy = by0 + r, gx = bx0 + c;
        float x = 0.f, y = 0.f;
        if ((unsigned)gy < IMH && (unsigned)gx < IMW) {
            int o = gy * IMW + gx;
            x = px[o];
            y = py[o];
        }
        int s = r * INS + c;
        sX[s] = x;
        sY[s] = y;
        if (r >= HALO && r < IN - HALO && c >= HALO && c < IN - HALO)
            l1 += fabsf(x - y);
    }
}

__global__ __launch_bounds__(256, 4) void ssim_l1_kernel(
    const float* __restrict__ pred, const float* __restrict__ tgt)
{
    extern __shared__ float sm[];
    float* sX = sm;                   // IN*INS each (raw inputs only)
    float* sY = sX + IN * INS;
    float* hX = sY + IN * INS;        // IN*TS each (H-pass results)
    float* hY = hX + IN * TS;
    float* hP = hY + IN * TS;         // H-conv of x^2+y^2
    float* hQ = hP + IN * TS;         // H-conv of x*y

    const int tid = threadIdx.x;
    float l1 = 0.f, ssim = 0.f;

    // ---- Prologue: load first tile.
    int t = blockIdx.x;
    load_tile(t, tid, pred, tgt, sX, sY, l1);
    __syncthreads();

    for (; t < NTILES; t += GRID) {
        // ---- Phase 2: horizontal pass, p/q derived in registers.
        //      42 rows x 8 groups of 4 cols = 336 items; 8x LDS.128 per item.
        for (int i = tid; i < IN * (TS / 4); i += 256) {
            int r  = i >> 3;
            int c0 = (i & 7) * 4;
            int b  = r * INS + c0;   // 16B-aligned: r*44 and c0 mult of 4
            int ho = r * TS + c0;    // 16B-aligned

            float xv[16], yv[16];
            {
                const float4* p4 = reinterpret_cast<const float4*>(sX + b);
#pragma unroll
                for (int j = 0; j < 4; j++) {
                    float4 a = p4[j];
                    xv[4*j] = a.x; xv[4*j+1] = a.y; xv[4*j+2] = a.z; xv[4*j+3] = a.w;
                }
                const float4* q4 = reinterpret_cast<const float4*>(sY + b);
#pragma unroll
                for (int j = 0; j < 4; j++) {
                    float4 a = q4[j];
                    yv[4*j] = a.x; yv[4*j+1] = a.y; yv[4*j+2] = a.z; yv[4*j+3] = a.w;
                }
            }
            float4 o;
            conv16to4(xv, o); *reinterpret_cast<float4*>(hX + ho) = o;
            conv16to4(yv, o); *reinterpret_cast<float4*>(hY + ho) = o;
            // overwrite windows in place: xv <- x^2+y^2, yv <- x*y
#pragma unroll
            for (int j = 0; j < 16; j++) {
                float x = xv[j], y = yv[j];
                float q = x * y;
                xv[j] = x * x + y * y;
                yv[j] = q;
            }
            conv16to4(xv, o); *reinterpret_cast<float4*>(hP + ho) = o;
            conv16to4(yv, o); *reinterpret_cast<float4*>(hQ + ho) = o;
        }
        __syncthreads();

        // ---- Phase 3: vertical pass + SSIM accumulate (registers persist).
        //      32 cols x 8 groups of 4 rows = exactly 256 threads, all active.
        {
            int c  = tid & 31;
            int r0 = (tid >> 5) * 4;
            int b  = r0 * TS + c;

            float m1[4], m2[4], ep[4], eq[4];
#pragma unroll
            for (int m = 0; m < 4; m++) { m1[m] = 0.f; m2[m] = 0.f; ep[m] = 0.f; eq[m] = 0.f; }

#pragma unroll
            for (int j = 0; j < 14; j++) {
                int o = b + j * TS;
                float vx = hX[o];
                float vy = hY[o];
                float vp = hP[o];
                float vq = hQ[o];
#pragma unroll
                for (int m = 0; m < 4; m++) {
                    int k = j - m;
                    if (k >= 0 && k <= 10) {
                        float w = GW[k];
                        m1[m] += w * vx;
                        m2[m] += w * vy;
                        ep[m] += w * vp;
                        eq[m] += w * vq;
                    }
                }
            }
#pragma unroll
            for (int j = 0; j < 4; j++) {
                float m11 = m1[j] * m1[j];
                float m22 = m2[j] * m2[j];
                float m12 = m1[j] * m2[j];
                float s12 = eq[j] - m12;          // sigma12
                float sss = ep[j] - m11 - m22;    // sigma1_sq + sigma2_sq
                const float C1 = 1e-4f;   // 0.01^2
                const float C2 = 9e-4f;   // 0.03^2
                float num = (2.f * m12 + C1) * (2.f * s12 + C2);
                float den = (m11 + m22 + C1) * (sss + C2);
                ssim += __fdividef(num, den);
            }
        }

        // ---- Pipelined prologue: load NEXT tile while V-pass retires.
        //      p1(t+GRID) writes sX/sY, which only p2(t) read (done pre-barrier).
        int tn = t + GRID;
        if (tn < NTILES)
            load_tile(tn, tid, pred, tgt, sX, sY, l1);
        __syncthreads();   // orders: h reads (p3) before p2(t+GRID) overwrites;
                           // sX/sY writes before p2(t+GRID) reads
    }

    // ---- Once per block: reduce (l1, ssim), one atomicAdd pair.
#pragma unroll
    for (int off = 16; off > 0; off >>= 1) {
        l1   += __shfl_down_sync(0xffffffffu, l1,   off);
        ssim += __shfl_down_sync(0xffffffffu, ssim, off);
    }
    int warp = tid >> 5;
    int lane = tid & 31;
    if (lane == 0) {          // sX dead: last reader (p2) finished before exit
        sX[warp]     = l1;
        sX[8 + warp] = ssim;
    }
    __syncthreads();
    if (tid == 0) {
        double a = 0.0, b = 0.0;
#pragma unroll
        for (int w = 0; w < 8; w++) { a += (double)sX[w]; b += (double)sX[8 + w]; }
        atomicAdd(&g_acc[0], a);
        atomicAdd(&g_acc[1], b);
    }
}

__global__ void finalize_kernel(float* __restrict__ out) {
    const double n = (double)NPIX;
    double l1 = g_acc[0] / n;
    double ss = g_acc[1] / n;
    out[0] = (float)(0.84 * l1 + (1.0 - 0.84) * (1.0 - ss));
    g_acc[0] = 0.0;   // reset for the next replay (keeps launches deterministic)
    g_acc[1] = 0.0;
}

extern "C" void kernel_launch(void* const* d_in, const int* in_sizes, int n_in,
                              void* d_out, int out_size)
{
    const float* pred = (const float*)d_in[0];
    const float* tgt  = (const float*)d_in[1];
    float* out = (float*)d_out;

    const int smem_bytes = (2 * IN * INS + 4 * IN * TS) * (int)sizeof(float); // 36288
    cudaFuncSetAttribute(ssim_l1_kernel,
                         cudaFuncAttributeMaxDynamicSharedMemorySize, smem_bytes);

    ssim_l1_kernel<<<GRID, 256, smem_bytes>>>(pred, tgt);
    finalize_kernel<<<1, 1>>>(out);
}

// round 17
// speedup vs baseline: 1.2497x; 1.0194x over previous
#include <cuda_runtime.h>

#define TS   32          // output tile (TS x TS)
#define HALO 5
#define IN   42          // TS + 2*HALO
#define INS  44          // padded smem row stride for input arrays (mult of 4)
#define IMH  512
#define IMW  512
#define NPLANES (32*3)
#define NPIX    ((long long)NPLANES * IMH * IMW)   // 25165824
#define NTILES  (16 * 16 * NPLANES)               // 24576
#define GRID    592                               // 148 SM x 4 CTA: one wave

typedef unsigned long long u64;

// Normalized 11-tap Gaussian (sigma=1.5), compile-time so taps become FFMA-imm.
__device__ constexpr float GW[11] = {
    0.00102838f, 0.00759876f, 0.03600077f, 0.10936071f, 0.21300550f,
    0.26601172f,
    0.21300550f, 0.10936071f, 0.03600077f, 0.00759876f, 0.00102838f
};

// [0] = sum |x-y|, [1] = sum ssim_map. Zero-initialized at module load;
// finalize_kernel resets them after reading, so every replay starts from 0.
__device__ double g_acc[2] = {0.0, 0.0};

__device__ __forceinline__ u64 pack2(float lo, float hi) {
    u64 r; asm("mov.b64 %0, {%1, %2};" : "=l"(r) : "f"(lo), "f"(hi)); return r;
}
__device__ __forceinline__ void unpack2(u64 v, float& lo, float& hi) {
    asm("mov.b64 {%0, %1}, %2;" : "=f"(lo), "=f"(hi) : "l"(v));
}
__device__ __forceinline__ void fma2(u64& acc, u64 w, u64 v) {
    asm("fma.rn.f32x2 %0, %1, %2, %0;" : "+l"(acc) : "l"(w), "l"(v));
}

// Sliding-window conv on a 16-value register window: outputs cols j..j+3.
__device__ __forceinline__ void conv16to4(const float* __restrict__ v, float4& out)
{
    float o0 = 0.f, o1 = 0.f, o2 = 0.f, o3 = 0.f;
#pragma unroll
    for (int k = 0; k < 11; k++) {
        float w = GW[k];
        o0 += w * v[k];
        o1 += w * v[k + 1];
        o2 += w * v[k + 2];
        o3 += w * v[k + 3];
    }
    out.x = o0; out.y = o1; out.z = o2; out.w = o3;
}

// Load tile t's 42x42 halo region into sX/sY; fold L1 for interior pixels.
__device__ __forceinline__ void load_tile(
    int t, int tid, const float* __restrict__ pred, const float* __restrict__ tgt,
    float* __restrict__ sX, float* __restrict__ sY, float& l1)
{
    int plane = t >> 8;               // 256 tiles per plane (16x16)
    int rem   = t & 255;
    int by0   = (rem >> 4) * TS - HALO;
    int bx0   = (rem & 15) * TS - HALO;
    const float* __restrict__ px = pred + (size_t)plane * (IMH * IMW);
    const float* __restrict__ py = tgt  + (size_t)plane * (IMH * IMW);

    for (int i = tid; i < IN * IN; i += 256) {
        int r = i / IN;
        int c = i - r * IN;
        int gy = by0 + r, gx = bx0 + c;
        float x = 0.f, y = 0.f;
        if ((unsigned)gy < IMH && (unsigned)gx < IMW) {
            int o = gy * IMW + gx;
            x = px[o];
            y = py[o];
        }
        int s = r * INS + c;
        sX[s] = x;
        sY[s] = y;
        if (r >= HALO && r < IN - HALO && c >= HALO && c < IN - HALO)
            l1 += fabsf(x - y);
    }
}

__global__ __launch_bounds__(256, 4) void ssim_l1_kernel(
    const float* __restrict__ pred, const float* __restrict__ tgt)
{
    extern __shared__ float sm[];
    float* sX = sm;                   // IN*INS each (raw inputs only)
    float* sY = sX + IN * INS;
    float* hX = sY + IN * INS;        // IN*TS each (H-pass results)
    float* hY = hX + IN * TS;
    float* hP = hY + IN * TS;         // H-conv of x^2+y^2
    float* hQ = hP + IN * TS;         // H-conv of x*y

    const int tid = threadIdx.x;
    float l1 = 0.f, ssim = 0.f;

    // ---- Prologue: load first tile.
    int t = blockIdx.x;
    load_tile(t, tid, pred, tgt, sX, sY, l1);
    __syncthreads();

    for (; t < NTILES; t += GRID) {
        // ---- Phase 2: horizontal pass, p/q derived in registers.
        //      42 rows x 8 groups of 4 cols = 336 items; 8x LDS.128 per item.
        for (int i = tid; i < IN * (TS / 4); i += 256) {
            int r  = i >> 3;
            int c0 = (i & 7) * 4;
            int b  = r * INS + c0;   // 16B-aligned: r*44 and c0 mult of 4
            int ho = r * TS + c0;    // 16B-aligned

            float xv[16], yv[16];
            {
                const float4* p4 = reinterpret_cast<const float4*>(sX + b);
#pragma unroll
                for (int j = 0; j < 4; j++) {
                    float4 a = p4[j];
                    xv[4*j] = a.x; xv[4*j+1] = a.y; xv[4*j+2] = a.z; xv[4*j+3] = a.w;
                }
                const float4* q4 = reinterpret_cast<const float4*>(sY + b);
#pragma unroll
                for (int j = 0; j < 4; j++) {
                    float4 a = q4[j];
                    yv[4*j] = a.x; yv[4*j+1] = a.y; yv[4*j+2] = a.z; yv[4*j+3] = a.w;
                }
            }
            float4 o;
            conv16to4(xv, o); *reinterpret_cast<float4*>(hX + ho) = o;
            conv16to4(yv, o); *reinterpret_cast<float4*>(hY + ho) = o;
            // overwrite windows in place: xv <- x^2+y^2, yv <- x*y
#pragma unroll
            for (int j = 0; j < 16; j++) {
                float x = xv[j], y = yv[j];
                float q = x * y;
                xv[j] = x * x + y * y;
                yv[j] = q;
            }
            conv16to4(xv, o); *reinterpret_cast<float4*>(hP + ho) = o;
            conv16to4(yv, o); *reinterpret_cast<float4*>(hQ + ho) = o;
        }
        __syncthreads();

        // ---- Phase 3: vertical pass + SSIM, f32x2-paired.
        //      (hX,hY) and (hP,hQ) share weights -> FFMA2 halves the conv FMAs.
        //      32 cols x 8 groups of 4 rows = exactly 256 threads, all active.
        {
            int c  = tid & 31;
            int r0 = (tid >> 5) * 4;
            int b  = r0 * TS + c;

            // 6 unique packed weights (GW is symmetric), registers only.
            u64 w2[6];
#pragma unroll
            for (int k = 0; k < 6; k++) w2[k] = pack2(GW[k], GW[k]);

            u64 m12[4], epq[4];
#pragma unroll
            for (int m = 0; m < 4; m++) { m12[m] = 0ull; epq[m] = 0ull; }

#pragma unroll
            for (int j = 0; j < 14; j++) {
                int o = b + j * TS;
                u64 vxy = pack2(hX[o], hY[o]);
                u64 vpq = pack2(hP[o], hQ[o]);
#pragma unroll
                for (int m = 0; m < 4; m++) {
                    int k = j - m;
                    if (k >= 0 && k <= 10) {
                        u64 w = w2[k <= 5 ? k : 10 - k];
                        fma2(m12[m], w, vxy);
                        fma2(epq[m], w, vpq);
                    }
                }
            }
#pragma unroll
            for (int j = 0; j < 4; j++) {
                float mu1, mu2, ep, eq;
                unpack2(m12[j], mu1, mu2);
                unpack2(epq[j], ep, eq);
                float m11 = mu1 * mu1;
                float m22 = mu2 * mu2;
                float mab = mu1 * mu2;
                float s12 = eq - mab;             // sigma12
                float sss = ep - m11 - m22;       // sigma1_sq + sigma2_sq
                const float C1 = 1e-4f;   // 0.01^2
                const float C2 = 9e-4f;   // 0.03^2
                float num = (2.f * mab + C1) * (2.f * s12 + C2);
                float den = (m11 + m22 + C1) * (sss + C2);
                ssim += __fdividef(num, den);
            }
        }

        // ---- Pipelined prologue: load NEXT tile while V-pass retires.
        //      p1(t+GRID) writes sX/sY, which only p2(t) read (done pre-barrier).
        int tn = t + GRID;
        if (tn < NTILES)
            load_tile(tn, tid, pred, tgt, sX, sY, l1);
        __syncthreads();   // orders: h reads (p3) before p2(t+GRID) overwrites;
                           // sX/sY writes before p2(t+GRID) reads
    }

    // ---- Once per block: reduce (l1, ssim), one atomicAdd pair.
#pragma unroll
    for (int off = 16; off > 0; off >>= 1) {
        l1   += __shfl_down_sync(0xffffffffu, l1,   off);
        ssim += __shfl_down_sync(0xffffffffu, ssim, off);
    }
    int warp = tid >> 5;
    int lane = tid & 31;
    if (lane == 0) {          // sX dead: last reader (p2) finished before exit
        sX[warp]     = l1;
        sX[8 + warp] = ssim;
    }
    __syncthreads();
    if (tid == 0) {
        double a = 0.0, b = 0.0;
#pragma unroll
        for (int w = 0; w < 8; w++) { a += (double)sX[w]; b += (double)sX[8 + w]; }
        atomicAdd(&g_acc[0], a);
        atomicAdd(&g_acc[1], b);
    }
}

__global__ void finalize_kernel(float* __restrict__ out) {
    const double n = (double)NPIX;
    double l1 = g_acc[0] / n;
    double ss = g_acc[1] / n;
    out[0] = (float)(0.84 * l1 + (1.0 - 0.84) * (1.0 - ss));
    g_acc[0] = 0.0;   // reset for the next replay (keeps launches deterministic)
    g_acc[1] = 0.0;
}

extern "C" void kernel_launch(void* const* d_in, const int* in_sizes, int n_in,
                              void* d_out, int out_size)
{
    const float* pred = (const float*)d_in[0];
    const float* tgt  = (const float*)d_in[1];
    float* out = (float*)d_out;

    const int smem_bytes = (2 * IN * INS + 4 * IN * TS) * (int)sizeof(float); // 36288
    cudaFuncSetAttribute(ssim_l1_kernel,
                         cudaFuncAttributeMaxDynamicSharedMemorySize, smem_bytes);

    ssim_l1_kernel<<<GRID, 256, smem_bytes>>>(pred, tgt);
    finalize_kernel<<<1, 1>>>(out);
}